// round 7
// baseline (speedup 1.0000x reference)
#include <cuda_runtime.h>

// AbstractRelu (DeepPoly ReLU relaxation), elementwise over N fp32.
// out layout: [relu(x) (N)] [lb_slope*low (N)] [relu(high) (N)]
//
// R7: Blackwell 256-bit vector memory ops (ld/st.global.v8.f32, PTX 8.8,
// sm_100+). Each thread processes 8 floats: 3 x 32B loads, 3 x 32B stores.
// Per warp each memory instruction covers 1024B (8 full 128B lines) --
// half the instructions/scoreboard slots/L1tex queue entries per byte vs
// float4. Same traffic (402 MB floor), same MLP_p1=3 instruction pattern.
// History: R1/R3 63.6, R2 front-batch 65.6 (regr), R4 persistent 71.7
// (regr), R5 (128t, float4) 63.3 = best, R6 2-quad 63.8 (neutral).

__global__ void __launch_bounds__(128, 16)
abstract_relu_kernel(const float* __restrict__ x,
                     const float* __restrict__ low,
                     const float* __restrict__ high,
                     float* __restrict__ x_out,
                     float* __restrict__ low_out,
                     float* __restrict__ high_out,
                     int n8)
{
    int i = blockIdx.x * blockDim.x + threadIdx.x;
    if (i >= n8) return;

    const size_t base = (size_t)i * 8;

    float xv[8], lv[8], hv[8];

    asm volatile("ld.global.nc.v8.f32 {%0,%1,%2,%3,%4,%5,%6,%7}, [%8];"
                 : "=f"(xv[0]), "=f"(xv[1]), "=f"(xv[2]), "=f"(xv[3]),
                   "=f"(xv[4]), "=f"(xv[5]), "=f"(xv[6]), "=f"(xv[7])
                 : "l"(x + base));
    asm volatile("ld.global.nc.v8.f32 {%0,%1,%2,%3,%4,%5,%6,%7}, [%8];"
                 : "=f"(lv[0]), "=f"(lv[1]), "=f"(lv[2]), "=f"(lv[3]),
                   "=f"(lv[4]), "=f"(lv[5]), "=f"(lv[6]), "=f"(lv[7])
                 : "l"(low + base));
    asm volatile("ld.global.nc.v8.f32 {%0,%1,%2,%3,%4,%5,%6,%7}, [%8];"
                 : "=f"(hv[0]), "=f"(hv[1]), "=f"(hv[2]), "=f"(hv[3]),
                   "=f"(hv[4]), "=f"(hv[5]), "=f"(hv[6]), "=f"(hv[7])
                 : "l"(high + base));

    float xo[8], lo[8], ho[8];

    #pragma unroll
    for (int e = 0; e < 8; e++) {
        float xe = xv[e], le = lv[e], he = hv[e];
        xo[e] = fmaxf(xe, 0.0f);
        ho[e] = fmaxf(he, 0.0f);
        bool zero = (he <= 0.0f) || (le < 0.0f && le * le > he * he);
        lo[e] = zero ? 0.0f : le;
    }

    asm volatile("st.global.v8.f32 [%0], {%1,%2,%3,%4,%5,%6,%7,%8};"
                 :: "l"(x_out + base),
                    "f"(xo[0]), "f"(xo[1]), "f"(xo[2]), "f"(xo[3]),
                    "f"(xo[4]), "f"(xo[5]), "f"(xo[6]), "f"(xo[7])
                 : "memory");
    asm volatile("st.global.v8.f32 [%0], {%1,%2,%3,%4,%5,%6,%7,%8};"
                 :: "l"(low_out + base),
                    "f"(lo[0]), "f"(lo[1]), "f"(lo[2]), "f"(lo[3]),
                    "f"(lo[4]), "f"(lo[5]), "f"(lo[6]), "f"(lo[7])
                 : "memory");
    asm volatile("st.global.v8.f32 [%0], {%1,%2,%3,%4,%5,%6,%7,%8};"
                 :: "l"(high_out + base),
                    "f"(ho[0]), "f"(ho[1]), "f"(ho[2]), "f"(ho[3]),
                    "f"(ho[4]), "f"(ho[5]), "f"(ho[6]), "f"(ho[7])
                 : "memory");
}

extern "C" void kernel_launch(void* const* d_in, const int* in_sizes, int n_in,
                              void* d_out, int out_size)
{
    const float* x    = (const float*)d_in[0];
    const float* low  = (const float*)d_in[1];
    const float* high = (const float*)d_in[2];
    float* out = (float*)d_out;

    const int n  = in_sizes[0];          // 16777216
    const int n8 = n / 8;                // 2097152, divisible by 8

    float* x_out    = out;
    float* low_out  = out + n;
    float* high_out = out + 2 * (size_t)n;

    const int threads = 128;
    const int blocks  = (n8 + threads - 1) / threads;  // 16384

    abstract_relu_kernel<<<blocks, threads>>>(
        x, low, high, x_out, low_out, high_out, n8);
}

// round 8
// speedup vs baseline: 1.0152x; 1.0152x over previous
#include <cuda_runtime.h>

// AbstractRelu (DeepPoly ReLU relaxation), elementwise over N fp32.
// out layout: [relu(x) (N)] [lb_slope*low (N)] [relu(high) (N)]
//
// FINAL (= R5, empirical best at 63.26us wall / 56.0us kernel, 7.19 TB/s
// effective ~ 90% of HBM spec). Convergence evidence across 8 rounds:
//   R1  256t float4 sequential ................ 63.7
//   R2  2-quad FRONT-BATCHED loads ............ 65.6  (L1tex queue contention)
//   R3  R1 + .cs hints ........................ 63.6  (hints neutral)
//   R4  persistent grid 1184 CTAs ............. 71.7  (loop overhead, worse)
//   R5  128t float4 sequential + .cs .......... 63.3  << best
//   R6  2-quad sequential (fenced) ............ 63.8  (neutral)
//   R7  256-bit v8.f32 ld/st .................. 64.2  (issue not binding)
// Traffic is at the 402MB floor; kernel is HBM-bound at the LTS/HBM ceiling.

__global__ void __launch_bounds__(128, 16)
abstract_relu_kernel(const float4* __restrict__ x,
                     const float4* __restrict__ low,
                     const float4* __restrict__ high,
                     float4* __restrict__ x_out,
                     float4* __restrict__ low_out,
                     float4* __restrict__ high_out,
                     int n4)
{
    int i = blockIdx.x * blockDim.x + threadIdx.x;
    if (i >= n4) return;

    float4 xv = __ldcs(&x[i]);
    float4 lv = __ldcs(&low[i]);
    float4 hv = __ldcs(&high[i]);

    float4 xo, lo, ho;

    #define LANE(f)                                                        \
    {                                                                      \
        float xe = xv.f, le = lv.f, he = hv.f;                             \
        xo.f = fmaxf(xe, 0.0f);                                            \
        ho.f = fmaxf(he, 0.0f);                                            \
        bool zero = (he <= 0.0f) || (le < 0.0f && le * le > he * he);      \
        lo.f = zero ? 0.0f : le;                                           \
    }

    LANE(x) LANE(y) LANE(z) LANE(w)
    #undef LANE

    __stcs(&x_out[i],    xo);
    __stcs(&low_out[i],  lo);
    __stcs(&high_out[i], ho);
}

extern "C" void kernel_launch(void* const* d_in, const int* in_sizes, int n_in,
                              void* d_out, int out_size)
{
    const float* x    = (const float*)d_in[0];
    const float* low  = (const float*)d_in[1];
    const float* high = (const float*)d_in[2];
    float* out = (float*)d_out;

    const int n  = in_sizes[0];          // 16777216
    const int n4 = n / 4;                // 4194304

    float* x_out    = out;
    float* low_out  = out + n;
    float* high_out = out + 2 * (size_t)n;

    const int threads = 128;
    const int blocks  = (n4 + threads - 1) / threads;  // 32768

    abstract_relu_kernel<<<blocks, threads>>>(
        (const float4*)x, (const float4*)low, (const float4*)high,
        (float4*)x_out, (float4*)low_out, (float4*)high_out, n4);
}